// round 16
// baseline (speedup 1.0000x reference)
#include <cuda_runtime.h>
#include <cuda_bf16.h>
#include <math.h>
#include <stdint.h>

// Problem constants
#define B_    8
#define S_    64
#define T_    512
#define HID_  4096
#define NH_   32
#define NKV_  32
#define D_    128
#define HIST_ 2048
#define BSZ_  64
#define NBLK_ 33
#define L_    2112
#define QKVW  12288   // 3 * HID_

__device__ float g_qkv[(size_t)T_ * QKVW];
__device__ float g_attn[(size_t)T_ * HID_];
// Pre-converted activation tiles: 4 mblk x 128 chunks x 16KB (hi 8K | lo 8K)
__device__ __align__(16) char g_xt[(size_t)8388608];

// ==================================================================
// Helpers
// ==================================================================
__device__ __forceinline__ uint32_t smem_u32(const void* p) {
    return (uint32_t)__cvta_generic_to_shared(p);
}
__device__ __forceinline__ uint32_t pack_bf2(float x0, float x1) {
    uint32_t d;
    asm("cvt.rn.bf16x2.f32 %0, %1, %2;" : "=r"(d) : "f"(x1), "f"(x0));
    return d;
}
__device__ __forceinline__ float2 unpack_bf2(uint32_t u) {
    float2 r;
    r.x = __uint_as_float(u << 16);
    r.y = __uint_as_float(u & 0xffff0000u);
    return r;
}
__device__ __forceinline__ void split4(float4 v, uint32_t* hi, uint32_t* lo) {
    uint32_t h0 = pack_bf2(v.x, v.y);
    uint32_t h1 = pack_bf2(v.z, v.w);
    float2 f0 = unpack_bf2(h0), f1 = unpack_bf2(h1);
    hi[0] = h0; hi[1] = h1;
    lo[0] = pack_bf2(v.x - f0.x, v.y - f0.y);
    lo[1] = pack_bf2(v.z - f1.x, v.w - f1.y);
}
__device__ __forceinline__ void ldsm4(uint32_t* r, uint32_t addr) {
    asm volatile("ldmatrix.sync.aligned.m8n8.x4.shared.b16 {%0,%1,%2,%3}, [%4];"
                 : "=r"(r[0]), "=r"(r[1]), "=r"(r[2]), "=r"(r[3]) : "r"(addr));
}
__device__ __forceinline__ void ldsm4t(uint32_t* r, uint32_t addr) {
    asm volatile("ldmatrix.sync.aligned.m8n8.x4.trans.shared.b16 {%0,%1,%2,%3}, [%4];"
                 : "=r"(r[0]), "=r"(r[1]), "=r"(r[2]), "=r"(r[3]) : "r"(addr));
}
__device__ __forceinline__ void mma16816(float* d, const uint32_t* a, const uint32_t* b) {
    asm("mma.sync.aligned.m16n8k16.row.col.f32.bf16.bf16.f32 "
        "{%0,%1,%2,%3}, {%4,%5,%6,%7}, {%8,%9}, {%0,%1,%2,%3};"
        : "+f"(d[0]), "+f"(d[1]), "+f"(d[2]), "+f"(d[3])
        : "r"(a[0]), "r"(a[1]), "r"(a[2]), "r"(a[3]),
          "r"(b[0]), "r"(b[1]));
}
__device__ __forceinline__ void cpa16(uint32_t dst, const void* src) {
    asm volatile("cp.async.cg.shared.global [%0], [%1], 16;"
                 :: "r"(dst), "l"(src));
}
#define CP_COMMIT() asm volatile("cp.async.commit_group;" ::: "memory")
#define CP_WAIT1()  asm volatile("cp.async.wait_group 1;" ::: "memory")

// ==================================================================
// conv_a: fp32 [512,4096] -> bf16 hi/lo swizzled 16KB tiles
// ==================================================================
__global__ __launch_bounds__(256) void conv_a(const float* __restrict__ A,
                                              char* __restrict__ out)
{
    int idx = blockIdx.x * 256 + threadIdx.x;   // 512 rows * 512 k8 groups
    int row = idx >> 9, k8 = idx & 511;
    float4 v0 = *(const float4*)(A + (size_t)row * HID_ + k8 * 8);
    float4 v1 = *(const float4*)(A + (size_t)row * HID_ + k8 * 8 + 4);
    uint32_t h[4], l[4];
    split4(v0, h, l);
    split4(v1, h + 2, l + 2);
    int row_local = row & 127, mblk = row >> 7;
    int c = k8 >> 2, c16 = k8 & 3;
    int off = row_local * 64 + ((c16 ^ ((row_local >> 1) & 3)) << 4);
    char* base = out + (size_t)(mblk * 128 + c) * 16384;
    *(uint4*)(base + off)        = make_uint4(h[0], h[1], h[2], h[3]);
    *(uint4*)(base + 8192 + off) = make_uint4(l[0], l[1], l[2], l[3]);
}

// ==================================================================
// Warp-specialized GEMM (R14 winner, unchanged): 384 threads.
// ==================================================================
#define BKC 32
#define NCH (HID_ / BKC)      // 128
#define ATILE 16384
#define BTILE 16384
#define GSMEM  (4 * ATILE + 2 * BTILE + 128)

__global__ __launch_bounds__(384, 1)
void gemm_ws(const char* __restrict__ Xt,
             const float* __restrict__ B0, const float* __restrict__ B1,
             const float* __restrict__ B2,
             float* __restrict__ C, int Nper, int Ntot)
{
    extern __shared__ char dynsm[];
    uint32_t sraw = smem_u32(dynsm);
    uint32_t smb = (sraw + 127u) & ~127u;
    uint32_t aBase = smb;
    uint32_t bBase = smb + 4 * ATILE;
    char* smp = dynsm + (smb - sraw);

    int tid = threadIdx.x, lane = tid & 31, wid = tid >> 5;
    int mblk = blockIdx.y;
    int m0 = mblk * 128, col0 = blockIdx.x * 128;
    bool producer = (wid >= 8);

    const float* Bp; int nloc;
    if (col0 < Nper)          { Bp = B0; nloc = col0; }
    else if (col0 < 2 * Nper) { Bp = B1; nloc = col0 - Nper; }
    else                      { Bp = B2; nloc = col0 - 2 * Nper; }
    size_t NperS = (size_t)Nper;

    int pt = tid - 256;
    const float* Bptr = Bp + nloc + (pt & 127);
    int rxB = ((pt & 127) >> 1) & 3;
    const char* aSrcBase = Xt + (size_t)mblk * 128 * ATILE + (pt & 127) * 128;
    uint32_t aDstOff = (uint32_t)((pt & 127) * 128);
    float pb[32];

    int wm = wid & 1, wn = wid >> 1;
    int aRow = wm * 64 + ((lane >> 3) & 1) * 8 + (lane & 7);
    int aCh  = (lane >> 4) & 1;
    int aRX  = (aRow >> 1) & 3;
    uint32_t aOff = (uint32_t)(aRow * 64);
    int nbRow = wn * 32 + ((lane >> 4) & 1) * 8 + (lane & 7);
    int bCh  = (lane >> 3) & 1;
    int bRX  = (nbRow >> 1) & 3;
    uint32_t nbOff = (uint32_t)(nbRow * 64);

    float acc[4][4][4];
#pragma unroll
    for (int i = 0; i < 4; i++)
#pragma unroll
        for (int j = 0; j < 4; j++)
#pragma unroll
            for (int e = 0; e < 4; e++) acc[i][j][e] = 0.f;

    if (producer) {
#pragma unroll
        for (int j = 0; j < 32; j++) pb[j] = Bptr[(size_t)j * NperS];
        {
            char* bb = smp + 4 * ATILE;
#pragma unroll
            for (int c16 = 0; c16 < 4; c16++) {
                uint32_t h[2], l[2], h2[2], l2[2];
                split4(make_float4(pb[c16*8+0], pb[c16*8+1], pb[c16*8+2], pb[c16*8+3]), h, l);
                split4(make_float4(pb[c16*8+4], pb[c16*8+5], pb[c16*8+6], pb[c16*8+7]), h2, l2);
                int off = (pt & 127) * 64 + ((c16 ^ rxB) << 4);
                *(uint4*)(bb + off)        = make_uint4(h[0], h[1], h2[0], h2[1]);
                *(uint4*)(bb + 8192 + off) = make_uint4(l[0], l[1], l2[0], l2[1]);
            }
        }
#pragma unroll
        for (int j = 0; j < 32; j++) pb[j] = Bptr[(size_t)(BKC + j) * NperS];
#pragma unroll
        for (int s = 0; s < 2; s++) {
            uint32_t dst = aBase + s * ATILE + aDstOff;
            const char* src = aSrcBase + (size_t)s * ATILE;
#pragma unroll
            for (int q = 0; q < 8; q++) cpa16(dst + q * 16, src + q * 16);
            CP_COMMIT();
        }
        CP_WAIT1();
    }
    __syncthreads();

    for (int c = 0; c < NCH; c++) {
        if (producer) {
            if (c + 1 < NCH) {
                char* bb = smp + 4 * ATILE + ((c + 1) & 1) * BTILE;
#pragma unroll
                for (int c16 = 0; c16 < 4; c16++) {
                    uint32_t h[2], l[2], h2[2], l2[2];
                    split4(make_float4(pb[c16*8+0], pb[c16*8+1], pb[c16*8+2], pb[c16*8+3]), h, l);
                    split4(make_float4(pb[c16*8+4], pb[c16*8+5], pb[c16*8+6], pb[c16*8+7]), h2, l2);
                    int off = (pt & 127) * 64 + ((c16 ^ rxB) << 4);
                    *(uint4*)(bb + off)        = make_uint4(h[0], h[1], h2[0], h2[1]);
                    *(uint4*)(bb + 8192 + off) = make_uint4(l[0], l[1], l2[0], l2[1]);
                }
            }
            if (c + 2 < NCH) {
                const float* bp = Bptr + (size_t)((c + 2) * BKC) * NperS;
#pragma unroll
                for (int j = 0; j < 32; j++) pb[j] = bp[(size_t)j * NperS];
                uint32_t dst = aBase + ((c + 2) & 3) * ATILE + aDstOff;
                const char* src = aSrcBase + (size_t)(c + 2) * ATILE;
#pragma unroll
                for (int q = 0; q < 8; q++) cpa16(dst + q * 16, src + q * 16);
            }
            CP_COMMIT();
            CP_WAIT1();
        } else {
            uint32_t stageA = aBase + (c & 3) * ATILE;
            uint32_t stageB = bBase + (c & 1) * BTILE;
#pragma unroll
            for (int s = 0; s < 2; s++) {
                uint32_t bfh[4][2], bfl[4][2];
#pragma unroll
                for (int half = 0; half < 2; half++) {
                    uint32_t addr = stageB + half * 1024 + nbOff
                                  + ((((s * 2) + bCh) ^ bRX) << 4);
                    uint32_t r[4];
                    ldsm4(r, addr);
                    bfh[half * 2][0] = r[0]; bfh[half * 2][1] = r[1];
                    bfh[half * 2 + 1][0] = r[2]; bfh[half * 2 + 1][1] = r[3];
                    ldsm4(r, addr + 8192);
                    bfl[half * 2][0] = r[0]; bfl[half * 2][1] = r[1];
                    bfl[half * 2 + 1][0] = r[2]; bfl[half * 2 + 1][1] = r[3];
                }
                uint32_t ahb[2][4], alb[2][4];
                {
                    uint32_t addr = stageA + aOff
                                  + ((((s * 2) + aCh) ^ aRX) << 4);
                    ldsm4(ahb[0], addr);
                    ldsm4(alb[0], addr + 8192);
                }
#pragma unroll
                for (int mt = 0; mt < 4; mt++) {
                    int cur = mt & 1;
                    if (mt < 3) {
                        uint32_t addr = stageA + (mt + 1) * 1024 + aOff
                                      + ((((s * 2) + aCh) ^ aRX) << 4);
                        ldsm4(ahb[cur ^ 1], addr);
                        ldsm4(alb[cur ^ 1], addr + 8192);
                    }
#pragma unroll
                    for (int nt = 0; nt < 4; nt++) mma16816(acc[mt][nt], ahb[cur], bfh[nt]);
#pragma unroll
                    for (int nt = 0; nt < 4; nt++) mma16816(acc[mt][nt], ahb[cur], bfl[nt]);
#pragma unroll
                    for (int nt = 0; nt < 4; nt++) mma16816(acc[mt][nt], alb[cur], bfh[nt]);
                }
            }
        }
        __syncthreads();
    }

    if (!producer) {
#pragma unroll
        for (int mt = 0; mt < 4; mt++) {
            int row = m0 + wm * 64 + mt * 16 + (lane >> 2);
#pragma unroll
            for (int nt = 0; nt < 4; nt++) {
                int col = col0 + wn * 32 + nt * 8 + (lane & 3) * 2;
                *(float2*)(C + (size_t)row * Ntot + col) =
                    make_float2(acc[mt][nt][0], acc[mt][nt][1]);
                *(float2*)(C + (size_t)(row + 8) * Ntot + col) =
                    make_float2(acc[mt][nt][2], acc[mt][nt][3]);
            }
        }
    }
}

// ------------------------------------------------------------------
// RoPE in place on q/k of g_qkv.
// ------------------------------------------------------------------
__global__ __launch_bounds__(256) void rope_k(const int* __restrict__ pos_ids)
{
    int idx = blockIdx.x * 256 + threadIdx.x;
    int i = idx & 63;
    int h = (idx >> 6) & 63;
    int t = idx >> 12;
    if (t >= T_) return;

    float p = (float)pos_ids[t];
    float inv = expf((float)i * (-9.210340371976184f / 64.0f));
    float ang = p * inv;
    float s, c;
    sincosf(ang, &s, &c);

    size_t base = (size_t)t * QKVW + (size_t)h * D_ + i;
    float x0 = g_qkv[base];
    float x1 = g_qkv[base + 64];
    g_qkv[base]      = x0 * c - x1 * s;
    g_qkv[base + 64] = x1 * c + x0 * s;
}

// ==================================================================
// Tensor-core flash attention: 256 threads, 8 warps, 2 CTAs/SM.
// Single KV buffer (K and V alternate). 4 syncs per tile:
//   [K STS] sync [QK + S] sync [softmax + V STS] sync [PV] sync
// Warp map: wm=wid&3 (16 q rows), wn=wid>>2 (32 keys QK / 64 dims PV).
// ==================================================================
#define AQH 0u
#define AQL 16384u
#define KVH 32768u
#define KVL 49152u
#define ASS 65536u            // S: 64*68 fp32 = 17408 B (ends 82944)
#define APH 82944u
#define APL 91136u
#define AST 99328u            // stats 1024 B
#define ATTN_SMEM 100480

__device__ __forceinline__ void kv_src(int t, int b, int n,
                                       const float* cache,
                                       const int* __restrict__ block_offsets,
                                       int qkv_off,
                                       const float*& ptr, size_t& str)
{
    if (t < 32) {
        int blk = block_offsets[b * NBLK_ + t];
        ptr = cache + ((size_t)blk * BSZ_ * NKV_ + n) * D_;
        str = (size_t)NKV_ * D_;
    } else {
        ptr = g_qkv + (size_t)b * S_ * QKVW + qkv_off + (size_t)n * D_;
        str = QKVW;
    }
}

__global__ __launch_bounds__(256, 2) void attn_tc(
    const float* __restrict__ k_cache, const float* __restrict__ v_cache,
    const int* __restrict__ pos_ids, const int* __restrict__ block_offsets)
{
    extern __shared__ char smc[];
    uint32_t smb = smem_u32(smc);
    float* s_s   = (float*)(smc + ASS);
    float* row_m = (float*)(smc + AST);
    float* row_l = row_m + 64;
    float* row_c = row_l + 64;
    int*   pos_s = (int*)(row_c + 64);

    int n = blockIdx.x, b = blockIdx.y;
    int tid = threadIdx.x, lane = tid & 31, wid = tid >> 5;
    int wm = wid & 3, wn = wid >> 2;

    // ---- prologue: Q -> smem, stats ----
    const float* qbase = g_qkv + (size_t)b * S_ * QKVW + (size_t)n * D_;
#pragma unroll
    for (int i = 0; i < 8; i++) {
        int e = i * 256 + tid;
        int row = e >> 5, q = e & 31;
        int off = row * 256 + (((q >> 1) ^ (row & 7)) << 4) + (q & 1) * 8;
        float4 v = *(const float4*)(qbase + (size_t)row * QKVW + q * 4);
        uint32_t h[2], l[2];
        split4(v, h, l);
        *(uint2*)(smc + AQH + off) = make_uint2(h[0], h[1]);
        *(uint2*)(smc + AQL + off) = make_uint2(l[0], l[1]);
    }
    if (tid < 64) {
        row_m[tid] = -3.0e38f;
        row_l[tid] = 0.f;
        pos_s[tid] = pos_ids[b * S_ + tid];
    }

    float accO[8][4];
#pragma unroll
    for (int i = 0; i < 8; i++)
#pragma unroll
        for (int e = 0; e < 4; e++) accO[i][e] = 0.f;

    const float scale = 0.08838834764831845f;

    int arow  = wm * 16 + ((lane >> 3) & 1) * 8 + (lane & 7);
    int brow0 = wn * 32 + ((lane >> 4) & 1) * 8 + (lane & 7);
    int prow  = arow;
    int vkeyb = ((lane >> 3) & 1) * 8 + (lane & 7);
    int achq  = (lane >> 4) & 1;
    int bchq  = (lane >> 3) & 1;

    for (int t = 0; t < 33; t++) {
        // ===== phase 1: K(t) -> KV buffer =====
        {
            const float* kb; size_t kstr;
            kv_src(t, b, n, k_cache, block_offsets, HID_, kb, kstr);
#pragma unroll
            for (int i = 0; i < 8; i++) {
                int e = i * 256 + tid;
                int row = e >> 5, q = e & 31;
                int off = row * 256 + (((q >> 1) ^ (row & 7)) << 4) + (q & 1) * 8;
                float4 w = *(const float4*)(kb + (size_t)row * kstr + q * 4);
                uint32_t h[2], l[2];
                split4(w, h, l);
                *(uint2*)(smc + KVH + off) = make_uint2(h[0], h[1]);
                *(uint2*)(smc + KVL + off) = make_uint2(l[0], l[1]);
            }
        }
        __syncthreads();

        // ===== phase 2: S = Q K^T =====
        {
            float accs[4][4];
#pragma unroll
            for (int i = 0; i < 4; i++)
#pragma unroll
                for (int e = 0; e < 4; e++) accs[i][e] = 0.f;

#pragma unroll
            for (int ks = 0; ks < 8; ks++) {
                uint32_t ah[4], al[4];
                uint32_t aaddr = smb + AQH + arow * 256
                               + (((2 * ks + achq) ^ (arow & 7)) << 4);
                ldsm4(ah, aaddr);
                ldsm4(al, aaddr + (AQL - AQH));
                uint32_t bh[4][2], bl[4][2];
#pragma unroll
                for (int half = 0; half < 2; half++) {
                    int brow = brow0 + half * 16;
                    uint32_t baddr = smb + KVH + brow * 256
                                   + (((2 * ks + bchq) ^ (brow & 7)) << 4);
                    uint32_t r[4];
                    ldsm4(r, baddr);
                    bh[half * 2][0] = r[0]; bh[half * 2][1] = r[1];
                    bh[half * 2 + 1][0] = r[2]; bh[half * 2 + 1][1] = r[3];
                    ldsm4(r, baddr + (KVL - KVH));
                    bl[half * 2][0] = r[0]; bl[half * 2][1] = r[1];
                    bl[half * 2 + 1][0] = r[2]; bl[half * 2 + 1][1] = r[3];
                }
#pragma unroll
                for (int nt = 0; nt < 4; nt++) mma16816(accs[nt], ah, bh[nt]);
#pragma unroll
                for (int nt = 0; nt < 4; nt++) mma16816(accs[nt], ah, bl[nt]);
#pragma unroll
                for (int nt = 0; nt < 4; nt++) mma16816(accs[nt], al, bh[nt]);
            }
            int r0 = wm * 16 + (lane >> 2);
            int c0 = wn * 32 + (lane & 3) * 2;
#pragma unroll
            for (int nt = 0; nt < 4; nt++) {
                *(float2*)&s_s[r0 * 68 + c0 + nt * 8] =
                    make_float2(accs[nt][0] * scale, accs[nt][1] * scale);
                *(float2*)&s_s[(r0 + 8) * 68 + c0 + nt * 8] =
                    make_float2(accs[nt][2] * scale, accs[nt][3] * scale);
            }
        }
        __syncthreads();

        // ===== phase 3: V(t) -> KV buffer || online softmax =====
        {
            const float* vb; size_t vstr;
            kv_src(t, b, n, v_cache, block_offsets, 2 * HID_, vb, vstr);
#pragma unroll
            for (int i = 0; i < 8; i++) {
                int e = i * 256 + tid;
                int row = e >> 5, q = e & 31;
                int off = row * 256 + (((q >> 1) ^ (row & 7)) << 4) + (q & 1) * 8;
                float4 w = *(const float4*)(vb + (size_t)row * vstr + q * 4);
                uint32_t h[2], l[2];
                split4(w, h, l);
                *(uint2*)(smc + KVH + off) = make_uint2(h[0], h[1]);
                *(uint2*)(smc + KVL + off) = make_uint2(l[0], l[1]);
            }
        }
        {
            int r = tid >> 2, u = tid & 3;
            int lb = t * 64, pr = pos_s[r];
            bool nm = (lb + 63 > pr);
            float p16[16];
            float mloc = -3.0e38f;
#pragma unroll
            for (int jj = 0; jj < 16; jj++) {
                int j = u * 16 + jj;
                float sv = s_s[r * 68 + j];
                p16[jj] = sv;
                if (!nm || lb + j <= pr) mloc = fmaxf(mloc, sv);
            }
            mloc = fmaxf(mloc, __shfl_xor_sync(0xffffffffu, mloc, 1));
            mloc = fmaxf(mloc, __shfl_xor_sync(0xffffffffu, mloc, 2));
            float mnew = fmaxf(row_m[r], mloc);
            float sum = 0.f;
#pragma unroll
            for (int jj = 0; jj < 16; jj++) {
                int j = u * 16 + jj;
                float pv = 0.f;
                if (!nm || lb + j <= pr) pv = expf(p16[jj] - mnew);
                p16[jj] = pv;
                sum += pv;
            }
            sum += __shfl_xor_sync(0xffffffffu, sum, 1);
            sum += __shfl_xor_sync(0xffffffffu, sum, 2);
#pragma unroll
            for (int cc = 0; cc < 2; cc++) {
                uint32_t hw[4], lw[4];
#pragma unroll
                for (int qd = 0; qd < 4; qd++) {
                    float x0 = p16[cc * 8 + qd * 2], x1 = p16[cc * 8 + qd * 2 + 1];
                    hw[qd] = pack_bf2(x0, x1);
                    float2 f = unpack_bf2(hw[qd]);
                    lw[qd] = pack_bf2(x0 - f.x, x1 - f.y);
                }
                int off = r * 128 + (((2 * u + cc) ^ (r & 7)) << 4);
                *(uint4*)(smc + APH + off) = make_uint4(hw[0], hw[1], hw[2], hw[3]);
                *(uint4*)(smc + APL + off) = make_uint4(lw[0], lw[1], lw[2], lw[3]);
            }
            if (u == 0) {
                float corr = expf(row_m[r] - mnew);
                row_c[r] = corr;
                row_l[r] = row_l[r] * corr + sum;
                row_m[r] = mnew;
            }
        }
        __syncthreads();

        // ===== phase 4: O = O*corr + P V =====
        {
            float c0f = row_c[wm * 16 + (lane >> 2)];
            float c1f = row_c[wm * 16 + (lane >> 2) + 8];
#pragma unroll
            for (int nt = 0; nt < 8; nt++) {
                accO[nt][0] *= c0f; accO[nt][1] *= c0f;
                accO[nt][2] *= c1f; accO[nt][3] *= c1f;
            }
#pragma unroll
            for (int ks = 0; ks < 4; ks++) {
                uint32_t pha[4], pla[4];
                uint32_t paddr = smb + APH + prow * 128
                               + (((2 * ks + achq) ^ (prow & 7)) << 4);
                ldsm4(pha, paddr);
                ldsm4(pla, paddr + (APL - APH));
                int key = ks * 16 + vkeyb;
#pragma unroll
                for (int pr2 = 0; pr2 < 4; pr2++) {
                    int dch = wn * 8 + pr2 * 2 + achq;
                    uint32_t vaddr = smb + KVH + key * 256
                                   + ((dch ^ (key & 7)) << 4);
                    uint32_t rh[4], rl[4];
                    ldsm4t(rh, vaddr);
                    ldsm4t(rl, vaddr + (KVL - KVH));
                    uint32_t bh0[2] = { rh[0], rh[1] }, bh1[2] = { rh[2], rh[3] };
                    uint32_t bl0[2] = { rl[0], rl[1] }, bl1[2] = { rl[2], rl[3] };
                    mma16816(accO[pr2 * 2],     pha, bh0);
                    mma16816(accO[pr2 * 2 + 1], pha, bh1);
                    mma16816(accO[pr2 * 2],     pha, bl0);
                    mma16816(accO[pr2 * 2 + 1], pha, bl1);
                    mma16816(accO[pr2 * 2],     pla, bh0);
                    mma16816(accO[pr2 * 2 + 1], pla, bh1);
                }
            }
        }
        __syncthreads();   // protect K(t+1) STS into KV
    }

    // ---- epilogue ----
    int r0 = wm * 16 + (lane >> 2);
    float il0 = 1.0f / row_l[r0];
    float il1 = 1.0f / row_l[r0 + 8];
    float* ob0 = g_attn + (size_t)(b * S_ + r0) * HID_ + (size_t)n * D_
               + wn * 64 + (lane & 3) * 2;
    float* ob1 = ob0 + 8 * HID_;
#pragma unroll
    for (int nt = 0; nt < 8; nt++) {
        *(float2*)(ob0 + nt * 8) = make_float2(accO[nt][0] * il0, accO[nt][1] * il0);
        *(float2*)(ob1 + nt * 8) = make_float2(accO[nt][2] * il1, accO[nt][3] * il1);
    }
}

// ------------------------------------------------------------------
// Launch
// ------------------------------------------------------------------
extern "C" void kernel_launch(void* const* d_in, const int* in_sizes, int n_in,
                              void* d_out, int out_size)
{
    const float* X  = (const float*)d_in[0];
    const float* kc = (const float*)d_in[1];
    const float* vc = (const float*)d_in[2];
    const float* wq = (const float*)d_in[3];
    const float* wk = (const float*)d_in[4];
    const float* wv = (const float*)d_in[5];
    const float* wo = (const float*)d_in[6];
    const int* pos  = (const int*)d_in[7];
    const int* bo   = (const int*)d_in[8];
    float* out = (float*)d_out;

    float *qkv_p, *attn_p;
    char *xt_p;
    cudaGetSymbolAddress((void**)&qkv_p, g_qkv);
    cudaGetSymbolAddress((void**)&attn_p, g_attn);
    cudaGetSymbolAddress((void**)&xt_p, g_xt);

    cudaFuncSetAttribute(gemm_ws, cudaFuncAttributeMaxDynamicSharedMemorySize,
                         GSMEM);
    cudaFuncSetAttribute(attn_tc, cudaFuncAttributeMaxDynamicSharedMemorySize,
                         ATTN_SMEM);

    // 0) convert X to bf16 hi/lo tiles
    conv_a<<<1024, 256>>>(X, xt_p);

    // 1) fused QKV projection (warp-specialized, 384 thr)
    gemm_ws<<<dim3(96, 4), 384, GSMEM>>>(xt_p, wq, wk, wv, qkv_p, HID_, QKVW);

    // 2) RoPE on q and k
    rope_k<<<(T_ * 64 * 64) / 256, 256>>>(pos);

    // 3) paged causal flash attention (256 thr, 2 CTAs/SM)
    attn_tc<<<dim3(NH_, B_), 256, ATTN_SMEM>>>(kc, vc, pos, bo);

    // 4) convert attention output + output projection
    conv_a<<<1024, 256>>>(attn_p, xt_p);
    gemm_ws<<<dim3(32, 4), 384, GSMEM>>>(xt_p, wo, wo, wo, out, HID_, HID_);
}

// round 17
// speedup vs baseline: 1.5613x; 1.5613x over previous
#include <cuda_runtime.h>
#include <cuda_bf16.h>
#include <math.h>
#include <stdint.h>

// Problem constants
#define B_    8
#define S_    64
#define T_    512
#define HID_  4096
#define NH_   32
#define NKV_  32
#define D_    128
#define HIST_ 2048
#define BSZ_  64
#define NBLK_ 33
#define L_    2112
#define QKVW  12288   // 3 * HID_

__device__ float g_qkv[(size_t)T_ * QKVW];
__device__ float g_attn[(size_t)T_ * HID_];
__device__ __align__(16) char g_xt[(size_t)8388608];

// ==================================================================
// Helpers
// ==================================================================
__device__ __forceinline__ uint32_t smem_u32(const void* p) {
    return (uint32_t)__cvta_generic_to_shared(p);
}
__device__ __forceinline__ uint32_t pack_bf2(float x0, float x1) {
    uint32_t d;
    asm("cvt.rn.bf16x2.f32 %0, %1, %2;" : "=r"(d) : "f"(x1), "f"(x0));
    return d;
}
__device__ __forceinline__ float2 unpack_bf2(uint32_t u) {
    float2 r;
    r.x = __uint_as_float(u << 16);
    r.y = __uint_as_float(u & 0xffff0000u);
    return r;
}
__device__ __forceinline__ void split4(float4 v, uint32_t* hi, uint32_t* lo) {
    uint32_t h0 = pack_bf2(v.x, v.y);
    uint32_t h1 = pack_bf2(v.z, v.w);
    float2 f0 = unpack_bf2(h0), f1 = unpack_bf2(h1);
    hi[0] = h0; hi[1] = h1;
    lo[0] = pack_bf2(v.x - f0.x, v.y - f0.y);
    lo[1] = pack_bf2(v.z - f1.x, v.w - f1.y);
}
__device__ __forceinline__ void ldsm4(uint32_t* r, uint32_t addr) {
    asm volatile("ldmatrix.sync.aligned.m8n8.x4.shared.b16 {%0,%1,%2,%3}, [%4];"
                 : "=r"(r[0]), "=r"(r[1]), "=r"(r[2]), "=r"(r[3]) : "r"(addr));
}
__device__ __forceinline__ void ldsm4t(uint32_t* r, uint32_t addr) {
    asm volatile("ldmatrix.sync.aligned.m8n8.x4.trans.shared.b16 {%0,%1,%2,%3}, [%4];"
                 : "=r"(r[0]), "=r"(r[1]), "=r"(r[2]), "=r"(r[3]) : "r"(addr));
}
__device__ __forceinline__ void mma16816(float* d, const uint32_t* a, const uint32_t* b) {
    asm("mma.sync.aligned.m16n8k16.row.col.f32.bf16.bf16.f32 "
        "{%0,%1,%2,%3}, {%4,%5,%6,%7}, {%8,%9}, {%0,%1,%2,%3};"
        : "+f"(d[0]), "+f"(d[1]), "+f"(d[2]), "+f"(d[3])
        : "r"(a[0]), "r"(a[1]), "r"(a[2]), "r"(a[3]),
          "r"(b[0]), "r"(b[1]));
}
__device__ __forceinline__ void cpa16(uint32_t dst, const void* src) {
    asm volatile("cp.async.cg.shared.global [%0], [%1], 16;"
                 :: "r"(dst), "l"(src));
}
#define CP_COMMIT() asm volatile("cp.async.commit_group;" ::: "memory")
#define CP_WAIT1()  asm volatile("cp.async.wait_group 1;" ::: "memory")
#define BAR64(id) asm volatile("bar.sync %0, 64;" :: "r"(id) : "memory")

// ==================================================================
// conv_a: fp32 [512,4096] -> bf16 hi/lo swizzled 16KB tiles
// ==================================================================
__global__ __launch_bounds__(256) void conv_a(const float* __restrict__ A,
                                              char* __restrict__ out)
{
    int idx = blockIdx.x * 256 + threadIdx.x;
    int row = idx >> 9, k8 = idx & 511;
    float4 v0 = *(const float4*)(A + (size_t)row * HID_ + k8 * 8);
    float4 v1 = *(const float4*)(A + (size_t)row * HID_ + k8 * 8 + 4);
    uint32_t h[4], l[4];
    split4(v0, h, l);
    split4(v1, h + 2, l + 2);
    int row_local = row & 127, mblk = row >> 7;
    int c = k8 >> 2, c16 = k8 & 3;
    int off = row_local * 64 + ((c16 ^ ((row_local >> 1) & 3)) << 4);
    char* base = out + (size_t)(mblk * 128 + c) * 16384;
    *(uint4*)(base + off)        = make_uint4(h[0], h[1], h[2], h[3]);
    *(uint4*)(base + 8192 + off) = make_uint4(l[0], l[1], l[2], l[3]);
}

// ==================================================================
// Warp-specialized GEMM (R14 winner, unchanged): 384 threads.
// ==================================================================
#define BKC 32
#define NCH (HID_ / BKC)
#define ATILE 16384
#define BTILE 16384
#define GSMEM  (4 * ATILE + 2 * BTILE + 128)

__global__ __launch_bounds__(384, 1)
void gemm_ws(const char* __restrict__ Xt,
             const float* __restrict__ B0, const float* __restrict__ B1,
             const float* __restrict__ B2,
             float* __restrict__ C, int Nper, int Ntot)
{
    extern __shared__ char dynsm[];
    uint32_t sraw = smem_u32(dynsm);
    uint32_t smb = (sraw + 127u) & ~127u;
    uint32_t aBase = smb;
    uint32_t bBase = smb + 4 * ATILE;
    char* smp = dynsm + (smb - sraw);

    int tid = threadIdx.x, lane = tid & 31, wid = tid >> 5;
    int mblk = blockIdx.y;
    int m0 = mblk * 128, col0 = blockIdx.x * 128;
    bool producer = (wid >= 8);

    const float* Bp; int nloc;
    if (col0 < Nper)          { Bp = B0; nloc = col0; }
    else if (col0 < 2 * Nper) { Bp = B1; nloc = col0 - Nper; }
    else                      { Bp = B2; nloc = col0 - 2 * Nper; }
    size_t NperS = (size_t)Nper;

    int pt = tid - 256;
    const float* Bptr = Bp + nloc + (pt & 127);
    int rxB = ((pt & 127) >> 1) & 3;
    const char* aSrcBase = Xt + (size_t)mblk * 128 * ATILE + (pt & 127) * 128;
    uint32_t aDstOff = (uint32_t)((pt & 127) * 128);
    float pb[32];

    int wm = wid & 1, wn = wid >> 1;
    int aRow = wm * 64 + ((lane >> 3) & 1) * 8 + (lane & 7);
    int aCh  = (lane >> 4) & 1;
    int aRX  = (aRow >> 1) & 3;
    uint32_t aOff = (uint32_t)(aRow * 64);
    int nbRow = wn * 32 + ((lane >> 4) & 1) * 8 + (lane & 7);
    int bCh  = (lane >> 3) & 1;
    int bRX  = (nbRow >> 1) & 3;
    uint32_t nbOff = (uint32_t)(nbRow * 64);

    float acc[4][4][4];
#pragma unroll
    for (int i = 0; i < 4; i++)
#pragma unroll
        for (int j = 0; j < 4; j++)
#pragma unroll
            for (int e = 0; e < 4; e++) acc[i][j][e] = 0.f;

    if (producer) {
#pragma unroll
        for (int j = 0; j < 32; j++) pb[j] = Bptr[(size_t)j * NperS];
        {
            char* bb = smp + 4 * ATILE;
#pragma unroll
            for (int c16 = 0; c16 < 4; c16++) {
                uint32_t h[2], l[2], h2[2], l2[2];
                split4(make_float4(pb[c16*8+0], pb[c16*8+1], pb[c16*8+2], pb[c16*8+3]), h, l);
                split4(make_float4(pb[c16*8+4], pb[c16*8+5], pb[c16*8+6], pb[c16*8+7]), h2, l2);
                int off = (pt & 127) * 64 + ((c16 ^ rxB) << 4);
                *(uint4*)(bb + off)        = make_uint4(h[0], h[1], h2[0], h2[1]);
                *(uint4*)(bb + 8192 + off) = make_uint4(l[0], l[1], l2[0], l2[1]);
            }
        }
#pragma unroll
        for (int j = 0; j < 32; j++) pb[j] = Bptr[(size_t)(BKC + j) * NperS];
#pragma unroll
        for (int s = 0; s < 2; s++) {
            uint32_t dst = aBase + s * ATILE + aDstOff;
            const char* src = aSrcBase + (size_t)s * ATILE;
#pragma unroll
            for (int q = 0; q < 8; q++) cpa16(dst + q * 16, src + q * 16);
            CP_COMMIT();
        }
        CP_WAIT1();
    }
    __syncthreads();

    for (int c = 0; c < NCH; c++) {
        if (producer) {
            if (c + 1 < NCH) {
                char* bb = smp + 4 * ATILE + ((c + 1) & 1) * BTILE;
#pragma unroll
                for (int c16 = 0; c16 < 4; c16++) {
                    uint32_t h[2], l[2], h2[2], l2[2];
                    split4(make_float4(pb[c16*8+0], pb[c16*8+1], pb[c16*8+2], pb[c16*8+3]), h, l);
                    split4(make_float4(pb[c16*8+4], pb[c16*8+5], pb[c16*8+6], pb[c16*8+7]), h2, l2);
                    int off = (pt & 127) * 64 + ((c16 ^ rxB) << 4);
                    *(uint4*)(bb + off)        = make_uint4(h[0], h[1], h2[0], h2[1]);
                    *(uint4*)(bb + 8192 + off) = make_uint4(l[0], l[1], l2[0], l2[1]);
                }
            }
            if (c + 2 < NCH) {
                const float* bp = Bptr + (size_t)((c + 2) * BKC) * NperS;
#pragma unroll
                for (int j = 0; j < 32; j++) pb[j] = bp[(size_t)j * NperS];
                uint32_t dst = aBase + ((c + 2) & 3) * ATILE + aDstOff;
                const char* src = aSrcBase + (size_t)(c + 2) * ATILE;
#pragma unroll
                for (int q = 0; q < 8; q++) cpa16(dst + q * 16, src + q * 16);
            }
            CP_COMMIT();
            CP_WAIT1();
        } else {
            uint32_t stageA = aBase + (c & 3) * ATILE;
            uint32_t stageB = bBase + (c & 1) * BTILE;
#pragma unroll
            for (int s = 0; s < 2; s++) {
                uint32_t bfh[4][2], bfl[4][2];
#pragma unroll
                for (int half = 0; half < 2; half++) {
                    uint32_t addr = stageB + half * 1024 + nbOff
                                  + ((((s * 2) + bCh) ^ bRX) << 4);
                    uint32_t r[4];
                    ldsm4(r, addr);
                    bfh[half * 2][0] = r[0]; bfh[half * 2][1] = r[1];
                    bfh[half * 2 + 1][0] = r[2]; bfh[half * 2 + 1][1] = r[3];
                    ldsm4(r, addr + 8192);
                    bfl[half * 2][0] = r[0]; bfl[half * 2][1] = r[1];
                    bfl[half * 2 + 1][0] = r[2]; bfl[half * 2 + 1][1] = r[3];
                }
                uint32_t ahb[2][4], alb[2][4];
                {
                    uint32_t addr = stageA + aOff
                                  + ((((s * 2) + aCh) ^ aRX) << 4);
                    ldsm4(ahb[0], addr);
                    ldsm4(alb[0], addr + 8192);
                }
#pragma unroll
                for (int mt = 0; mt < 4; mt++) {
                    int cur = mt & 1;
                    if (mt < 3) {
                        uint32_t addr = stageA + (mt + 1) * 1024 + aOff
                                      + ((((s * 2) + aCh) ^ aRX) << 4);
                        ldsm4(ahb[cur ^ 1], addr);
                        ldsm4(alb[cur ^ 1], addr + 8192);
                    }
#pragma unroll
                    for (int nt = 0; nt < 4; nt++) mma16816(acc[mt][nt], ahb[cur], bfh[nt]);
#pragma unroll
                    for (int nt = 0; nt < 4; nt++) mma16816(acc[mt][nt], ahb[cur], bfl[nt]);
#pragma unroll
                    for (int nt = 0; nt < 4; nt++) mma16816(acc[mt][nt], alb[cur], bfh[nt]);
                }
            }
        }
        __syncthreads();
    }

    if (!producer) {
#pragma unroll
        for (int mt = 0; mt < 4; mt++) {
            int row = m0 + wm * 64 + mt * 16 + (lane >> 2);
#pragma unroll
            for (int nt = 0; nt < 4; nt++) {
                int col = col0 + wn * 32 + nt * 8 + (lane & 3) * 2;
                *(float2*)(C + (size_t)row * Ntot + col) =
                    make_float2(acc[mt][nt][0], acc[mt][nt][1]);
                *(float2*)(C + (size_t)(row + 8) * Ntot + col) =
                    make_float2(acc[mt][nt][2], acc[mt][nt][3]);
            }
        }
    }
}

// ------------------------------------------------------------------
// RoPE in place on q/k of g_qkv.
// ------------------------------------------------------------------
__global__ __launch_bounds__(256) void rope_k(const int* __restrict__ pos_ids)
{
    int idx = blockIdx.x * 256 + threadIdx.x;
    int i = idx & 63;
    int h = (idx >> 6) & 63;
    int t = idx >> 12;
    if (t >= T_) return;

    float p = (float)pos_ids[t];
    float inv = expf((float)i * (-9.210340371976184f / 64.0f));
    float ang = p * inv;
    float s, c;
    sincosf(ang, &s, &c);

    size_t base = (size_t)t * QKVW + (size_t)h * D_ + i;
    float x0 = g_qkv[base];
    float x1 = g_qkv[base + 64];
    g_qkv[base]      = x0 * c - x1 * s;
    g_qkv[base + 64] = x1 * c + x0 * s;
}

// ==================================================================
// FA2-style attention: register-resident P, no S/P smem.
// 256 threads / 8 warps; wm=wid&3 (16 q rows), wn=wid>>2 (32 keys).
// Each warp computes partial O over its 32 keys for ALL 128 dims;
// the two wn-halves are summed in the epilogue.
// smem: Q hi/lo 32K, K hi/lo 32K, V hi/lo 32K, exch 1K -> 2 CTAs/SM.
// ==================================================================
#define AQH 0u
#define AQL 16384u
#define AKH 32768u
#define AKL 49152u
#define AVH 65536u
#define AVL 81920u
#define AEX 98304u            // exch: [4 wm][2 wn][32] floats = 1024 B
#define ATTN_SMEM 99456

__device__ __forceinline__ void kv_src(int t, int b, int n,
                                       const float* cache,
                                       const int* __restrict__ block_offsets,
                                       int qkv_off,
                                       const float*& ptr, size_t& str)
{
    if (t < 32) {
        int blk = block_offsets[b * NBLK_ + t];
        ptr = cache + ((size_t)blk * BSZ_ * NKV_ + n) * D_;
        str = (size_t)NKV_ * D_;
    } else {
        ptr = g_qkv + (size_t)b * S_ * QKVW + qkv_off + (size_t)n * D_;
        str = QKVW;
    }
}

__global__ __launch_bounds__(256, 2) void attn_tc(
    const float* __restrict__ k_cache, const float* __restrict__ v_cache,
    const int* __restrict__ pos_ids, const int* __restrict__ block_offsets)
{
    extern __shared__ char smc[];
    uint32_t smb = smem_u32(smc);
    float* exch = (float*)(smc + AEX);   // [wm][wn][32]

    int n = blockIdx.x, b = blockIdx.y;
    int tid = threadIdx.x, lane = tid & 31, wid = tid >> 5;
    int wm = wid & 3, wn = wid >> 2;

    // ---- prologue: Q -> smem ----
    const float* qbase = g_qkv + (size_t)b * S_ * QKVW + (size_t)n * D_;
#pragma unroll
    for (int i = 0; i < 8; i++) {
        int e = i * 256 + tid;
        int row = e >> 5, q = e & 31;
        int off = row * 256 + (((q >> 1) ^ (row & 7)) << 4) + (q & 1) * 8;
        float4 v = *(const float4*)(qbase + (size_t)row * QKVW + q * 4);
        uint32_t h[2], l[2];
        split4(v, h, l);
        *(uint2*)(smc + AQH + off) = make_uint2(h[0], h[1]);
        *(uint2*)(smc + AQL + off) = make_uint2(l[0], l[1]);
    }

    float accO[16][4];
#pragma unroll
    for (int i = 0; i < 16; i++)
#pragma unroll
        for (int e = 0; e < 4; e++) accO[i][e] = 0.f;

    float m_run[2] = { -3.0e38f, -3.0e38f };
    float l_run[2] = { 0.f, 0.f };

    const float scale = 0.08838834764831845f;

    int arow  = wm * 16 + ((lane >> 3) & 1) * 8 + (lane & 7);
    int brow0 = wn * 32 + ((lane >> 4) & 1) * 8 + (lane & 7);
    int vkeyb = ((lane >> 3) & 1) * 8 + (lane & 7);
    int achq  = (lane >> 4) & 1;
    int bchq  = (lane >> 3) & 1;
    int lrow  = lane >> 2;               // row-in-16 for stats (r0; r1=+8)
    int lc    = (lane & 3) * 2;          // col pair base within n8

    for (int t = 0; t < 33; t++) {
        // ===== phase 1: K(t) -> smem =====
        {
            const float* kb; size_t kstr;
            kv_src(t, b, n, k_cache, block_offsets, HID_, kb, kstr);
#pragma unroll
            for (int i = 0; i < 8; i++) {
                int e = i * 256 + tid;
                int row = e >> 5, q = e & 31;
                int off = row * 256 + (((q >> 1) ^ (row & 7)) << 4) + (q & 1) * 8;
                float4 w = *(const float4*)(kb + (size_t)row * kstr + q * 4);
                uint32_t h[2], l[2];
                split4(w, h, l);
                *(uint2*)(smc + AKH + off) = make_uint2(h[0], h[1]);
                *(uint2*)(smc + AKL + off) = make_uint2(l[0], l[1]);
            }
        }
        __syncthreads();

        // ===== phase 2: S = Q K^T (regs) ; then V(t) -> smem =====
        float accs[4][4];
#pragma unroll
        for (int i = 0; i < 4; i++)
#pragma unroll
            for (int e = 0; e < 4; e++) accs[i][e] = 0.f;

#pragma unroll
        for (int ks = 0; ks < 8; ks++) {
            uint32_t ah[4], al[4];
            uint32_t aaddr = smb + AQH + arow * 256
                           + (((2 * ks + achq) ^ (arow & 7)) << 4);
            ldsm4(ah, aaddr);
            ldsm4(al, aaddr + (AQL - AQH));
            uint32_t bh[4][2], bl[4][2];
#pragma unroll
            for (int half = 0; half < 2; half++) {
                int brow = brow0 + half * 16;
                uint32_t baddr = smb + AKH + brow * 256
                               + (((2 * ks + bchq) ^ (brow & 7)) << 4);
                uint32_t r[4];
                ldsm4(r, baddr);
                bh[half * 2][0] = r[0]; bh[half * 2][1] = r[1];
                bh[half * 2 + 1][0] = r[2]; bh[half * 2 + 1][1] = r[3];
                ldsm4(r, baddr + (AKL - AKH));
                bl[half * 2][0] = r[0]; bl[half * 2][1] = r[1];
                bl[half * 2 + 1][0] = r[2]; bl[half * 2 + 1][1] = r[3];
            }
#pragma unroll
            for (int nt = 0; nt < 4; nt++) mma16816(accs[nt], ah, bh[nt]);
#pragma unroll
            for (int nt = 0; nt < 4; nt++) mma16816(accs[nt], ah, bl[nt]);
#pragma unroll
            for (int nt = 0; nt < 4; nt++) mma16816(accs[nt], al, bh[nt]);
        }
        // V load/STS (independent of QK; PV waits on sync below)
        {
            const float* vb; size_t vstr;
            kv_src(t, b, n, v_cache, block_offsets, 2 * HID_, vb, vstr);
#pragma unroll
            for (int i = 0; i < 8; i++) {
                int e = i * 256 + tid;
                int row = e >> 5, q = e & 31;
                int off = row * 256 + (((q >> 1) ^ (row & 7)) << 4) + (q & 1) * 8;
                float4 w = *(const float4*)(vb + (size_t)row * vstr + q * 4);
                uint32_t h[2], l[2];
                split4(w, h, l);
                *(uint2*)(smc + AVH + off) = make_uint2(h[0], h[1]);
                *(uint2*)(smc + AVL + off) = make_uint2(l[0], l[1]);
            }
        }
        __syncthreads();

        // ===== phase 3: in-register softmax =====
        bool masked = (t == 32);
        float mloc[2] = { -3.0e38f, -3.0e38f };
#pragma unroll
        for (int nt = 0; nt < 4; nt++) {
#pragma unroll
            for (int e = 0; e < 4; e++) {
                float s = accs[nt][e] * scale;
                accs[nt][e] = s;
                int rr = (e >> 1);                     // 0 -> r0, 1 -> r1
                if (masked) {
                    int kloc = wn * 32 + nt * 8 + lc + (e & 1);
                    int rloc = wm * 16 + lrow + rr * 8;
                    if (kloc > rloc) continue;
                }
                mloc[rr] = fmaxf(mloc[rr], s);
            }
        }
#pragma unroll
        for (int rr = 0; rr < 2; rr++) {
            mloc[rr] = fmaxf(mloc[rr], __shfl_xor_sync(0xffffffffu, mloc[rr], 1));
            mloc[rr] = fmaxf(mloc[rr], __shfl_xor_sync(0xffffffffu, mloc[rr], 2));
        }
        if ((lane & 3) == 0) {
            exch[(wm * 2 + wn) * 32 + lrow]     = mloc[0];
            exch[(wm * 2 + wn) * 32 + 8 + lrow] = mloc[1];
        }
        BAR64(1 + wm);
        float mnew[2], corr[2];
#pragma unroll
        for (int rr = 0; rr < 2; rr++) {
            float mo = fmaxf(exch[(wm * 2 + 0) * 32 + rr * 8 + lrow],
                             exch[(wm * 2 + 1) * 32 + rr * 8 + lrow]);
            mnew[rr] = fmaxf(m_run[rr], mo);
            corr[rr] = expf(m_run[rr] - mnew[rr]);
            m_run[rr] = mnew[rr];
        }
        // exp + pack P fragments (hi/lo), accumulate sums
        uint32_t ph[2][4], pl[2][4];
        float sum[2] = { 0.f, 0.f };
#pragma unroll
        for (int kg = 0; kg < 2; kg++) {
#pragma unroll
            for (int half = 0; half < 2; half++) {       // nt = 2*kg + half
                int nt = 2 * kg + half;
#pragma unroll
                for (int rr = 0; rr < 2; rr++) {
                    float p0 = 0.f, p1 = 0.f;
                    bool ok0 = true, ok1 = true;
                    if (masked) {
                        int rloc = wm * 16 + lrow + rr * 8;
                        int kbase = wn * 32 + nt * 8 + lc;
                        ok0 = (kbase <= rloc);
                        ok1 = (kbase + 1 <= rloc);
                    }
                    if (ok0) p0 = expf(accs[nt][rr * 2 + 0] - mnew[rr]);
                    if (ok1) p1 = expf(accs[nt][rr * 2 + 1] - mnew[rr]);
                    sum[rr] += p0 + p1;
                    uint32_t hh = pack_bf2(p0, p1);
                    float2 f = unpack_bf2(hh);
                    ph[kg][half * 2 + rr] = hh;
                    pl[kg][half * 2 + rr] = pack_bf2(p0 - f.x, p1 - f.y);
                }
            }
        }
        // NOTE: a-frag order must be (r0 k0-7, r1 k0-7, r0 k8-15, r1 k8-15):
        // ph[kg] = { nt=2kg rr0, nt=2kg rr1, nt=2kg+1 rr0, nt=2kg+1 rr1 } ✓
#pragma unroll
        for (int rr = 0; rr < 2; rr++) {
            sum[rr] += __shfl_xor_sync(0xffffffffu, sum[rr], 1);
            sum[rr] += __shfl_xor_sync(0xffffffffu, sum[rr], 2);
        }
        if ((lane & 3) == 0) {
            exch[(wm * 2 + wn) * 32 + 16 + lrow] = sum[0];
            exch[(wm * 2 + wn) * 32 + 24 + lrow] = sum[1];
        }
        BAR64(1 + wm);
#pragma unroll
        for (int rr = 0; rr < 2; rr++) {
            float st = exch[(wm * 2 + 0) * 32 + 16 + rr * 8 + lrow]
                     + exch[(wm * 2 + 1) * 32 + 16 + rr * 8 + lrow];
            l_run[rr] = l_run[rr] * corr[rr] + st;
        }

        // ===== phase 4: O = O*corr + P V =====
#pragma unroll
        for (int ntl = 0; ntl < 16; ntl++) {
            accO[ntl][0] *= corr[0]; accO[ntl][1] *= corr[0];
            accO[ntl][2] *= corr[1]; accO[ntl][3] *= corr[1];
        }
#pragma unroll
        for (int kg = 0; kg < 2; kg++) {
            int key = wn * 32 + kg * 16 + vkeyb;
#pragma unroll
            for (int np = 0; np < 8; np++) {
                int dch = np * 2 + achq;
                uint32_t vaddr = smb + AVH + key * 256
                               + ((dch ^ (key & 7)) << 4);
                uint32_t rh[4], rl[4];
                ldsm4t(rh, vaddr);
                ldsm4t(rl, vaddr + (AVL - AVH));
                uint32_t bh0[2] = { rh[0], rh[1] }, bh1[2] = { rh[2], rh[3] };
                uint32_t bl0[2] = { rl[0], rl[1] }, bl1[2] = { rl[2], rl[3] };
                mma16816(accO[np * 2],     ph[kg], bh0);
                mma16816(accO[np * 2 + 1], ph[kg], bh1);
                mma16816(accO[np * 2],     ph[kg], bl0);
                mma16816(accO[np * 2 + 1], ph[kg], bl1);
                mma16816(accO[np * 2],     pl[kg], bh0);
                mma16816(accO[np * 2 + 1], pl[kg], bh1);
            }
        }
        __syncthreads();   // protect K(t+1)/V(t+1) overwrite
    }

    // ===== epilogue: cross-warp sum (wn halves) + normalize =====
    float* red = (float*)smc;   // reuse Q region: 64 rows x 128 dims fp32
    if (wn == 1) {
#pragma unroll
        for (int ntl = 0; ntl < 16; ntl++) {
            int dim = ntl * 8 + lc;
            *(float2*)&red[(wm * 16 + lrow) * 128 + dim] =
                make_float2(accO[ntl][0], accO[ntl][1]);
            *(float2*)&red[(wm * 16 + lrow + 8) * 128 + dim] =
                make_float2(accO[ntl][2], accO[ntl][3]);
        }
    }
    __syncthreads();
    if (wn == 0) {
        float il0 = 1.0f / l_run[0];
        float il1 = 1.0f / l_run[1];
        int r0 = wm * 16 + lrow;
        float* ob0 = g_attn + (size_t)(b * S_ + r0) * HID_ + (size_t)n * D_;
        float* ob1 = ob0 + 8 * HID_;
#pragma unroll
        for (int ntl = 0; ntl < 16; ntl++) {
            int dim = ntl * 8 + lc;
            float2 o0 = *(float2*)&red[r0 * 128 + dim];
            float2 o1 = *(float2*)&red[(r0 + 8) * 128 + dim];
            *(float2*)(ob0 + dim) = make_float2((accO[ntl][0] + o0.x) * il0,
                                                (accO[ntl][1] + o0.y) * il0);
            *(float2*)(ob1 + dim) = make_float2((accO[ntl][2] + o1.x) * il1,
                                                (accO[ntl][3] + o1.y) * il1);
        }
    }
}

// ------------------------------------------------------------------
// Launch
// ------------------------------------------------------------------
extern "C" void kernel_launch(void* const* d_in, const int* in_sizes, int n_in,
                              void* d_out, int out_size)
{
    const float* X  = (const float*)d_in[0];
    const float* kc = (const float*)d_in[1];
    const float* vc = (const float*)d_in[2];
    const float* wq = (const float*)d_in[3];
    const float* wk = (const float*)d_in[4];
    const float* wv = (const float*)d_in[5];
    const float* wo = (const float*)d_in[6];
    const int* pos  = (const int*)d_in[7];
    const int* bo   = (const int*)d_in[8];
    float* out = (float*)d_out;

    float *qkv_p, *attn_p;
    char *xt_p;
    cudaGetSymbolAddress((void**)&qkv_p, g_qkv);
    cudaGetSymbolAddress((void**)&attn_p, g_attn);
    cudaGetSymbolAddress((void**)&xt_p, g_xt);

    cudaFuncSetAttribute(gemm_ws, cudaFuncAttributeMaxDynamicSharedMemorySize,
                         GSMEM);
    cudaFuncSetAttribute(attn_tc, cudaFuncAttributeMaxDynamicSharedMemorySize,
                         ATTN_SMEM);

    // 0) convert X to bf16 hi/lo tiles
    conv_a<<<1024, 256>>>(X, xt_p);

    // 1) fused QKV projection (warp-specialized, 384 thr)
    gemm_ws<<<dim3(96, 4), 384, GSMEM>>>(xt_p, wq, wk, wv, qkv_p, HID_, QKVW);

    // 2) RoPE on q and k
    rope_k<<<(T_ * 64 * 64) / 256, 256>>>(pos);

    // 3) paged causal flash attention (FA2-style, 256 thr, 2 CTAs/SM)
    attn_tc<<<dim3(NH_, B_), 256, ATTN_SMEM>>>(kc, vc, pos, bo);

    // 4) convert attention output + output projection
    conv_a<<<1024, 256>>>(attn_p, xt_p);
    gemm_ws<<<dim3(32, 4), 384, GSMEM>>>(xt_p, wo, wo, wo, out, HID_, HID_);
}